// round 1
// baseline (speedup 1.0000x reference)
#include <cuda_runtime.h>
#include <cstddef>

#define BB 32
#define TT 2048
#define DD 512
#define HH 512
#define G4 2048
#define NCTA 128
#define JC 4

// Scratch (device globals are the sanctioned allocation-free scratch)
__device__ float g_i2h[(size_t)BB * TT * G4];   // 512 MB, reused by both layers
__device__ float g_y0[(size_t)TT * BB * HH];    // layer-0 output, [t][b][j]
__device__ float g_hbuf[2][HH * BB];            // double-buffered h, [j][b]
__device__ unsigned g_bar;
__device__ volatile unsigned g_epoch;

__global__ void init_state_kernel() {
    int i = blockIdx.x * blockDim.x + threadIdx.x;
    if (i < HH * BB) g_hbuf[0][i] = 0.f;
    if (i == 0) { g_bar = 0u; g_epoch = 0u; }
}

__device__ __forceinline__ float sigf(float x) { return 1.f / (1.f + __expf(-x)); }
__device__ __forceinline__ float tanhf_(float x) {
    x = fminf(15.f, fmaxf(-15.f, x));
    float e = __expf(2.f * x);
    return (e - 1.f) / (e + 1.f);
}

// C[M,2048] = A[M,512] @ W[2048,512]^T + bias ; M = 65536, tiles 128x128x16
__global__ __launch_bounds__(256, 2) void gemm_kernel(
    const float* __restrict__ A, const float* __restrict__ W,
    const float* __restrict__ bias, float* __restrict__ C)
{
    __shared__ float As[16][128];
    __shared__ float Ws[16][128];
    const int tid = threadIdx.x;
    const int tx = tid & 15, ty = tid >> 4;
    const int m0 = blockIdx.y * 128, n0 = blockIdx.x * 128;

    float acc[8][8];
    #pragma unroll
    for (int i = 0; i < 8; i++)
        #pragma unroll
        for (int j = 0; j < 8; j++) acc[i][j] = 0.f;

    const int lr = tid >> 1;          // 0..127 (tile row)
    const int lc = (tid & 1) * 2;     // float4-column base {0,2}

    for (int k0 = 0; k0 < DD; k0 += 16) {
        __syncthreads();
        #pragma unroll
        for (int l = 0; l < 2; l++) {
            int cc = lc + l;  // 0..3
            float4 va = *reinterpret_cast<const float4*>(&A[(size_t)(m0 + lr) * DD + k0 + cc * 4]);
            As[cc*4+0][lr] = va.x; As[cc*4+1][lr] = va.y;
            As[cc*4+2][lr] = va.z; As[cc*4+3][lr] = va.w;
            float4 vw = *reinterpret_cast<const float4*>(&W[(size_t)(n0 + lr) * DD + k0 + cc * 4]);
            Ws[cc*4+0][lr] = vw.x; Ws[cc*4+1][lr] = vw.y;
            Ws[cc*4+2][lr] = vw.z; Ws[cc*4+3][lr] = vw.w;
        }
        __syncthreads();
        #pragma unroll
        for (int k = 0; k < 16; k++) {
            float4 a0 = *reinterpret_cast<const float4*>(&As[k][ty * 8]);
            float4 a1 = *reinterpret_cast<const float4*>(&As[k][ty * 8 + 4]);
            float4 b0 = *reinterpret_cast<const float4*>(&Ws[k][tx * 8]);
            float4 b1 = *reinterpret_cast<const float4*>(&Ws[k][tx * 8 + 4]);
            float av[8] = {a0.x,a0.y,a0.z,a0.w,a1.x,a1.y,a1.z,a1.w};
            float bv[8] = {b0.x,b0.y,b0.z,b0.w,b1.x,b1.y,b1.z,b1.w};
            #pragma unroll
            for (int i = 0; i < 8; i++)
                #pragma unroll
                for (int j = 0; j < 8; j++)
                    acc[i][j] = fmaf(av[i], bv[j], acc[i][j]);
        }
    }
    float4 bs0 = *reinterpret_cast<const float4*>(&bias[n0 + tx*8]);
    float4 bs1 = *reinterpret_cast<const float4*>(&bias[n0 + tx*8 + 4]);
    #pragma unroll
    for (int i = 0; i < 8; i++) {
        size_t row = (size_t)(m0 + ty*8 + i) * G4 + n0 + tx*8;
        float4 o0 = make_float4(acc[i][0]+bs0.x, acc[i][1]+bs0.y, acc[i][2]+bs0.z, acc[i][3]+bs0.w);
        float4 o1 = make_float4(acc[i][4]+bs1.x, acc[i][5]+bs1.y, acc[i][6]+bs1.z, acc[i][7]+bs1.w);
        *reinterpret_cast<float4*>(&C[row])     = o0;
        *reinterpret_cast<float4*>(&C[row + 4]) = o1;
    }
}

// Persistent recurrence: 128 CTAs, CTA owns 4 hidden units (16 gate rows).
// ws: [k][16] gate-row weights (resident all steps). hs: [k][b] h broadcast.
__global__ __launch_bounds__(256, 1) void lstm_recur_kernel(
    const float* __restrict__ Wh, const float* __restrict__ bh,
    const float* __restrict__ i2h, float* __restrict__ yout,
    float* __restrict__ hc_out, int layer)
{
    extern __shared__ float sm[];
    float* ws  = sm;                 // 512*16
    float* hs  = ws + 512 * 16;      // 512*32
    float* red = hs + 512 * 32;      // 512*8
    float* bhs = red + 512 * 8;      // 16
    float* cs  = bhs + 16;           // 128

    const int tid = threadIdx.x;
    const int j0 = blockIdx.x * JC;

    {   // stage weights transposed: ws[k][r_loc], r_loc = g*4 + jj
        int rl = tid >> 4;
        int k0 = (tid & 15) * 32;
        int g = rl >> 2, jj = rl & 3;
        const float* wrow = Wh + (size_t)(g * HH + j0 + jj) * HH;
        #pragma unroll 8
        for (int kk = 0; kk < 32; kk++)
            ws[(k0 + kk) * 16 + rl] = wrow[k0 + kk];
        if (tid < 16) bhs[tid] = bh[(tid >> 2) * HH + j0 + (tid & 3)];
        if (tid < 128) cs[tid] = 0.f;
    }
    __syncthreads();

    const int ks = tid >> 5;           // K slice (64 k each), one per warp
    const int rt = (tid >> 3) & 3;     // row quad
    const int bt = tid & 7;            // batch quad
    const float4* ws4 = reinterpret_cast<const float4*>(ws);
    const float4* hs4 = reinterpret_cast<const float4*>(hs);

    for (int t = 0; t < TT; t++) {
        // stage h (L1-bypassing loads: L1 is stale across the global barrier)
        const float4* hsrc = reinterpret_cast<const float4*>(g_hbuf[t & 1]);
        float4* hdst = reinterpret_cast<float4*>(hs);
        #pragma unroll
        for (int i = 0; i < 16; i++)
            hdst[tid + i * 256] = __ldcg(&hsrc[tid + i * 256]);
        __syncthreads();

        float acc[4][4];
        #pragma unroll
        for (int ri = 0; ri < 4; ri++)
            #pragma unroll
            for (int bi = 0; bi < 4; bi++) acc[ri][bi] = 0.f;

        const int kend = ks * 64 + 64;
        #pragma unroll 8
        for (int k = ks * 64; k < kend; k++) {
            float4 hv = hs4[k * 8 + bt];   // 4 batches, broadcast across rt
            float4 wv = ws4[k * 4 + rt];   // 4 rows,    broadcast across bt
            acc[0][0] = fmaf(wv.x, hv.x, acc[0][0]);
            acc[0][1] = fmaf(wv.x, hv.y, acc[0][1]);
            acc[0][2] = fmaf(wv.x, hv.z, acc[0][2]);
            acc[0][3] = fmaf(wv.x, hv.w, acc[0][3]);
            acc[1][0] = fmaf(wv.y, hv.x, acc[1][0]);
            acc[1][1] = fmaf(wv.y, hv.y, acc[1][1]);
            acc[1][2] = fmaf(wv.y, hv.z, acc[1][2]);
            acc[1][3] = fmaf(wv.y, hv.w, acc[1][3]);
            acc[2][0] = fmaf(wv.z, hv.x, acc[2][0]);
            acc[2][1] = fmaf(wv.z, hv.y, acc[2][1]);
            acc[2][2] = fmaf(wv.z, hv.z, acc[2][2]);
            acc[2][3] = fmaf(wv.z, hv.w, acc[2][3]);
            acc[3][0] = fmaf(wv.w, hv.x, acc[3][0]);
            acc[3][1] = fmaf(wv.w, hv.y, acc[3][1]);
            acc[3][2] = fmaf(wv.w, hv.z, acc[3][2]);
            acc[3][3] = fmaf(wv.w, hv.w, acc[3][3]);
        }
        #pragma unroll
        for (int ri = 0; ri < 4; ri++)
            #pragma unroll
            for (int bi = 0; bi < 4; bi++)
                red[((rt * 4 + ri) * 32 + bt * 4 + bi) * 8 + ks] = acc[ri][bi];
        __syncthreads();

        if (tid < 128) {   // one thread per (b, jj)
            const int b  = tid & 31;
            const int jj = tid >> 5;
            const int j  = j0 + jj;
            const size_t mrow = (layer == 0) ? ((size_t)b * TT + t)
                                             : ((size_t)t * BB + b);
            const float* irow = i2h + mrow * G4 + j;
            float gate[4];
            #pragma unroll
            for (int g = 0; g < 4; g++) {
                const int rr = g * 4 + jj;
                const float4* rp = reinterpret_cast<const float4*>(&red[(rr * 32 + b) * 8]);
                float4 s0 = rp[0], s1 = rp[1];
                gate[g] = ((s0.x + s0.y) + (s0.z + s0.w))
                        + ((s1.x + s1.y) + (s1.z + s1.w))
                        + irow[g * HH] + bhs[rr];
            }
            float ig = sigf(gate[0]);
            float fg = sigf(gate[1]);
            float cg = tanhf_(gate[2]);
            float og = sigf(gate[3]);
            float c_new = fmaf(fg, cs[tid], ig * cg);
            float h_new = og * tanhf_(c_new);
            cs[tid] = c_new;
            g_hbuf[(t + 1) & 1][j * BB + b] = h_new;
            if (layer == 0)
                yout[((size_t)t * BB + b) * HH + j] = h_new;   // [t][b][j]
            else
                yout[((size_t)b * TT + t) * HH + j] = h_new;   // y1 [b][t][j]
            if (t == TT - 1) {
                hc_out[(size_t)layer * BB * HH + b * HH + j]       = h_new;
                hc_out[(size_t)(2 + layer) * BB * HH + b * HH + j] = c_new;
            }
        }

        if (t < TT - 1) {
            __threadfence();
            __syncthreads();
            if (tid == 0) {
                unsigned target = (unsigned)(t + 1) * NCTA;
                unsigned a = atomicAdd(&g_bar, 1u) + 1u;
                if (a == target) g_epoch = (unsigned)(t + 1);
                else while (g_epoch < (unsigned)(t + 1)) { }
            }
            __syncthreads();
        }
    }
}

extern "C" void kernel_launch(void* const* d_in, const int* in_sizes, int n_in,
                              void* d_out, int out_size)
{
    (void)in_sizes; (void)n_in; (void)out_size;
    const float* x   = (const float*)d_in[0];
    const float* Wi0 = (const float*)d_in[1];
    const float* bi0 = (const float*)d_in[2];
    const float* Wh0 = (const float*)d_in[3];
    const float* bh0 = (const float*)d_in[4];
    const float* Wi1 = (const float*)d_in[5];
    const float* bi1 = (const float*)d_in[6];
    const float* Wh1 = (const float*)d_in[7];
    const float* bh1 = (const float*)d_in[8];
    float* out = (float*)d_out;

    float *i2h_p, *y0_p;
    cudaGetSymbolAddress((void**)&i2h_p, g_i2h);
    cudaGetSymbolAddress((void**)&y0_p,  g_y0);

    const int SMEM = (512*16 + 512*32 + 512*8 + 16 + 128) * (int)sizeof(float);
    cudaFuncSetAttribute(lstm_recur_kernel,
                         cudaFuncAttributeMaxDynamicSharedMemorySize, SMEM);

    dim3 ggrid(G4 / 128, (BB * TT) / 128);
    float* hc = out + (size_t)BB * TT * HH;

    // Layer 0
    gemm_kernel<<<ggrid, 256>>>(x, Wi0, bi0, i2h_p);
    init_state_kernel<<<64, 256>>>();
    lstm_recur_kernel<<<NCTA, 256, SMEM>>>(Wh0, bh0, i2h_p, y0_p, hc, 0);
    // Layer 1
    gemm_kernel<<<ggrid, 256>>>(y0_p, Wi1, bi1, i2h_p);
    init_state_kernel<<<64, 256>>>();
    lstm_recur_kernel<<<NCTA, 256, SMEM>>>(Wh1, bh1, i2h_p, out, hc, 1);
}